// round 2
// baseline (speedup 1.0000x reference)
#include <cuda_runtime.h>
#include <cuda_bf16.h>

// Sorted segment-sum: values (N, 256) fp32, segment_ids (N) sorted int32 in [0, B),
// out (B, 256) fp32.  N = 1048576, B = 512 for this problem, but we only assume
// C == 256 (checked against out_size implicitly) and sortedness of ids.

#define C_COLS   256
#define CV       64      // float4 per row (256 floats)
#define RPB      512     // rows per block
#define UNR      8       // independent loads per thread per iteration (MLP)

__global__ void zero_out_kernel(float* __restrict__ out, int nelem) {
    int i = blockIdx.x * blockDim.x + threadIdx.x;
    if (i < nelem) out[i] = 0.0f;
}

__global__ __launch_bounds__(256)
void segsum_kernel(const float4* __restrict__ vals,
                   const int*    __restrict__ seg,
                   float*        __restrict__ out,
                   int n)
{
    __shared__ int sseg[RPB];

    const int row0 = blockIdx.x * RPB;
    int rows = n - row0;
    if (rows > RPB) rows = RPB;

    const int tid = threadIdx.y * 64 + threadIdx.x;
    for (int i = tid; i < rows; i += 256)
        sseg[i] = seg[row0 + i];
    __syncthreads();

    const int col = threadIdx.x;   // 0..63  (float4 column group)
    const int y   = threadIdx.y;   // 0..3   (row sub-stream)

    float4 acc = make_float4(0.f, 0.f, 0.f, 0.f);
    int cur = (y < rows) ? sseg[y] : -1;

    if (rows == RPB) {
        // fast path: full block, 16 iterations of 8-way-unrolled loads
        #pragma unroll 1
        for (int r = y; r < RPB; r += 4 * UNR) {
            float4 buf[UNR];
            #pragma unroll
            for (int u = 0; u < UNR; u++)
                buf[u] = vals[(size_t)(row0 + r + 4 * u) * CV + col];

            #pragma unroll
            for (int u = 0; u < UNR; u++) {
                const int s = sseg[r + 4 * u];
                if (s != cur) {
                    float* o = out + (size_t)cur * C_COLS + col * 4;
                    atomicAdd(o + 0, acc.x);
                    atomicAdd(o + 1, acc.y);
                    atomicAdd(o + 2, acc.z);
                    atomicAdd(o + 3, acc.w);
                    acc = make_float4(0.f, 0.f, 0.f, 0.f);
                    cur = s;
                }
                acc.x += buf[u].x;
                acc.y += buf[u].y;
                acc.z += buf[u].z;
                acc.w += buf[u].w;
            }
        }
    } else {
        // tail block: simple guarded loop
        for (int r = y; r < rows; r += 4) {
            float4 v = vals[(size_t)(row0 + r) * CV + col];
            const int s = sseg[r];
            if (s != cur) {
                float* o = out + (size_t)cur * C_COLS + col * 4;
                atomicAdd(o + 0, acc.x);
                atomicAdd(o + 1, acc.y);
                atomicAdd(o + 2, acc.z);
                atomicAdd(o + 3, acc.w);
                acc = make_float4(0.f, 0.f, 0.f, 0.f);
                cur = s;
            }
            acc.x += v.x;
            acc.y += v.y;
            acc.z += v.z;
            acc.w += v.w;
        }
    }

    if (cur >= 0) {
        float* o = out + (size_t)cur * C_COLS + col * 4;
        atomicAdd(o + 0, acc.x);
        atomicAdd(o + 1, acc.y);
        atomicAdd(o + 2, acc.z);
        atomicAdd(o + 3, acc.w);
    }
}

extern "C" void kernel_launch(void* const* d_in, const int* in_sizes, int n_in,
                              void* d_out, int out_size)
{
    const float* values = (const float*)d_in[0];
    const int*   segids = (const int*)d_in[1];
    // d_in[2] = num_segments (unused; out_size / 256 gives B)
    float* out = (float*)d_out;

    const int n = in_sizes[1];   // number of rows (= element count of segment_ids)

    // Output is poisoned; zero it first.
    {
        int threads = 256;
        int blocks = (out_size + threads - 1) / threads;
        zero_out_kernel<<<blocks, threads>>>(out, out_size);
    }

    dim3 block(64, 4);
    int grid = (n + RPB - 1) / RPB;
    segsum_kernel<<<grid, block>>>((const float4*)values, segids, out, n);
}

// round 3
// speedup vs baseline: 1.0268x; 1.0268x over previous
#include <cuda_runtime.h>
#include <cuda_bf16.h>

// Sorted segment-sum: values (N, 256) fp32, segment_ids (N) sorted int32 in [0, B),
// out (B, 256) fp32.  N = 1048576, B = 512. Stream-once HBM-bound kernel.

#define C_COLS   256
#define CV       64      // float4 per row (256 floats)
#define RPB      256     // rows per block (finer grain -> smaller scheduling tail)
#define UNR      8       // independent loads per thread per iteration (MLP)

__global__ void zero_out_kernel(float* __restrict__ out, int nelem) {
    int i = blockIdx.x * blockDim.x + threadIdx.x;
    if (i < nelem) out[i] = 0.0f;
}

// Vectorized fire-and-forget global reduction (sm_90+): one REDG.128 instead
// of four scalar atomics.
__device__ __forceinline__ void red_add_v4(float* addr, float4 v) {
    asm volatile("red.global.add.v4.f32 [%0], {%1, %2, %3, %4};"
                 :: "l"(addr), "f"(v.x), "f"(v.y), "f"(v.z), "f"(v.w)
                 : "memory");
}

__global__ __launch_bounds__(256)
void segsum_kernel(const float4* __restrict__ vals,
                   const int*    __restrict__ seg,
                   float*        __restrict__ out,
                   int n)
{
    __shared__ int sseg[RPB];

    const int row0 = blockIdx.x * RPB;
    int rows = n - row0;
    if (rows > RPB) rows = RPB;

    const int tid = threadIdx.y * 64 + threadIdx.x;
    if (tid < rows) sseg[tid] = seg[row0 + tid];
    __syncthreads();

    const int col = threadIdx.x;   // 0..63  (float4 column group)
    const int y   = threadIdx.y;   // 0..3   (row sub-stream)

    float4 acc = make_float4(0.f, 0.f, 0.f, 0.f);
    int cur = (y < rows) ? sseg[y] : -1;

    if (rows == RPB) {
        // fast path: full block, 8 iterations of 8-way front-batched streaming loads
        #pragma unroll 1
        for (int r = y; r < RPB; r += 4 * UNR) {
            float4 buf[UNR];
            #pragma unroll
            for (int u = 0; u < UNR; u++)
                buf[u] = __ldcs(&vals[(size_t)(row0 + r + 4 * u) * CV + col]);

            #pragma unroll
            for (int u = 0; u < UNR; u++) {
                const int s = sseg[r + 4 * u];
                if (s != cur) {
                    red_add_v4(out + (size_t)cur * C_COLS + col * 4, acc);
                    acc = make_float4(0.f, 0.f, 0.f, 0.f);
                    cur = s;
                }
                acc.x += buf[u].x;
                acc.y += buf[u].y;
                acc.z += buf[u].z;
                acc.w += buf[u].w;
            }
        }
    } else {
        // tail block: simple guarded loop
        for (int r = y; r < rows; r += 4) {
            float4 v = __ldcs(&vals[(size_t)(row0 + r) * CV + col]);
            const int s = sseg[r];
            if (s != cur) {
                red_add_v4(out + (size_t)cur * C_COLS + col * 4, acc);
                acc = make_float4(0.f, 0.f, 0.f, 0.f);
                cur = s;
            }
            acc.x += v.x;
            acc.y += v.y;
            acc.z += v.z;
            acc.w += v.w;
        }
    }

    if (cur >= 0)
        red_add_v4(out + (size_t)cur * C_COLS + col * 4, acc);
}

extern "C" void kernel_launch(void* const* d_in, const int* in_sizes, int n_in,
                              void* d_out, int out_size)
{
    const float* values = (const float*)d_in[0];
    const int*   segids = (const int*)d_in[1];
    float* out = (float*)d_out;

    const int n = in_sizes[1];   // number of rows (= element count of segment_ids)

    // Output is poisoned; zero it first (atomic flushes accumulate on top).
    {
        int threads = 256;
        int blocks = (out_size + threads - 1) / threads;
        zero_out_kernel<<<blocks, threads>>>(out, out_size);
    }

    dim3 block(64, 4);
    int grid = (n + RPB - 1) / RPB;
    segsum_kernel<<<grid, block>>>((const float4*)values, segids, out, n);
}